// round 12
// baseline (speedup 1.0000x reference)
#include <cuda_runtime.h>
#include <cstddef>
#include <cstdint>

#define IMGS 1280

__device__ float g_pool1[IMGS * 3 * 37 * 37];   // 21 MB scratch
__device__ float g_nf[IMGS * 6];
__device__ float g_sink;                        // DCE-blocker for L2 warmup

// ---- packed fp32x2 helpers (Blackwell) ----
__device__ __forceinline__ unsigned long long pk2(float lo, float hi) {
    unsigned long long d;
    asm("mov.b64 %0, {%1, %2};" : "=l"(d) : "f"(lo), "f"(hi));
    return d;
}
__device__ __forceinline__ void fma2(unsigned long long& d,
                                     unsigned long long a, unsigned long long b) {
    asm("fma.rn.f32x2 %0, %1, %2, %0;" : "+l"(d) : "l"(a), "l"(b));
}
__device__ __forceinline__ void upk2(unsigned long long v, float& lo, float& hi) {
    asm("mov.b64 {%0, %1}, %2;" : "=f"(lo), "=f"(hi) : "l"(v));
}

// ---------------------------------------------------------------------------
// Stage 1: conv1(3->3,k3,s2) + maxpool3 + relu via cp.async double-buffered
// smem pipeline. Grid = 1280 (one image/block), 128 threads.
// 19 groups of 2 pooled rows. Compute: lane pairs the group's two pooled rows
// (same q) into one fma.rn.f32x2 stream (cell pl0 in .lo, pl1 in .hi);
// compute warps rotate with g to balance SMSPs.
// ---------------------------------------------------------------------------
#define CHUNK_F   8736
#define S1_SMEM_FLOATS (2 * CHUNK_F + 96)
#define S1_SMEM_BYTES  (S1_SMEM_FLOATS * 4)

__device__ __forceinline__ void cp_async16(uint32_t saddr, const void* gptr) {
    asm volatile("cp.async.cg.shared.global [%0], [%1], 16;\n"
                 :: "r"(saddr), "l"(gptr));
}

__global__ __launch_bounds__(128, 3) void stage1_kernel(
    const float* __restrict__ nodes,
    const float* __restrict__ w1g,     // [oc][ci][3][3]
    const float* __restrict__ b1g)     // [3]
{
    extern __shared__ float sm[];
    float* w1s = sm + 2 * CHUNK_F;      // [ci][oc][kh][kw] (81)
    float* bsh = w1s + 81;              // [3]

    const int tid  = threadIdx.x;
    const int wid  = tid >> 5;
    const int lane = tid & 31;
    const int img  = blockIdx.x;

    if (tid < 81) {
        int oc = tid / 27, rem = tid - oc * 27;
        int ci = rem / 9,  k   = rem - ci * 9;
        w1s[ci * 27 + oc * 9 + k] = w1g[tid];
    }
    if (tid < 3) bsh[tid] = b1g[tid];

    const float* src = nodes + (size_t)img * 150528;
    const uint32_t s_base = (uint32_t)__cvta_generic_to_shared(sm);

    auto load_group = [&](int g) {
        const int r0   = 12 * g;
        const int cnt  = (g == 18) ? 7 : 13;          // input rows
        const int n4   = cnt * 56;                     // float4 per channel
        const uint32_t dbase = s_base + ((g & 1) * CHUNK_F) * 4;
#pragma unroll 1
        for (int ci = 0; ci < 3; ci++) {
            const float* gsrc = src + ci * 50176 + r0 * 224;
            const uint32_t dch = dbase + ci * (2912 * 4);
            for (int i = tid; i < n4; i += 128)
                cp_async16(dch + i * 16, gsrc + i * 4);
        }
        asm volatile("cp.async.commit_group;\n" ::: "memory");
    };

    load_group(0);

#pragma unroll 1
    for (int g = 0; g < 19; g++) {
        if (g + 1 < 19) {
            load_group(g + 1);
            asm volatile("cp.async.wait_group 1;\n" ::: "memory");
        } else {
            asm volatile("cp.async.wait_group 0;\n" ::: "memory");
        }
        __syncthreads();

        const int p_base = 2 * g;
        const int nrows  = (g == 18) ? 1 : 2;
        const float* buf = sm + (g & 1) * CHUNK_F;

        // rotated compute-warp assignment
        const int wA = g & 3, wB = (g + 1) & 3;
        int pairIdx = -1;
        if (wid == wA) pairIdx = lane;                         // pairs 0..31
        else if (wid == wB && lane < 5) pairIdx = 32 + lane;   // pairs 32..36

        if (pairIdx >= 0 && pairIdx < 37) {
            const int q = pairIdx;

            unsigned long long acc2[27];   // [oc*9 + pr*3 + pc]: lo=pl0, hi=pl1
#pragma unroll
            for (int j = 0; j < 27; j++) acc2[j] = 0ull;

#pragma unroll
            for (int ci = 0; ci < 3; ci++) {
                unsigned long long wp[27];
#pragma unroll
                for (int j = 0; j < 27; j++) {
                    float w = w1s[ci * 27 + j];
                    wp[j] = pk2(w, w);
                }

                const float* base = buf + ci * 2912 + 6 * q;
#pragma unroll
                for (int r = 0; r < 7; r++) {
                    // cell pl0 uses chunk row r; cell pl1 uses row r+6
                    const float2* rx = (const float2*)(base + r * 224);
                    const float2* ry = (const float2*)(base + (r + 6) * 224);
                    float2 x0 = rx[0], x1 = rx[1], x2 = rx[2], x3 = rx[3];
                    float2 y0 = ry[0], y1 = ry[1], y2 = ry[2], y3 = ry[3];
                    float vx[7] = {x0.x, x0.y, x1.x, x1.y, x2.x, x2.y, x3.x};
                    float vy[7] = {y0.x, y0.y, y1.x, y1.y, y2.x, y2.y, y3.x};
                    unsigned long long vp[7];
#pragma unroll
                    for (int c = 0; c < 7; c++) vp[c] = pk2(vx[c], vy[c]);

#pragma unroll
                    for (int pr = 0; pr < 3; pr++) {
                        const int kh = r - 2 * pr;
                        if (kh >= 0 && kh < 3) {
#pragma unroll
                            for (int oc = 0; oc < 3; oc++)
#pragma unroll
                                for (int pc = 0; pc < 3; pc++)
#pragma unroll
                                    for (int kw = 0; kw < 3; kw++)
                                        fma2(acc2[oc * 9 + pr * 3 + pc],
                                             vp[2 * pc + kw],
                                             wp[oc * 9 + kh * 3 + kw]);
                        }
                    }
                }
            }

            const size_t ob = (size_t)img * 4107 + (size_t)p_base * 37 + q;
#pragma unroll
            for (int oc = 0; oc < 3; oc++) {
                float mx = -1e30f, my = -1e30f;
#pragma unroll
                for (int k = 0; k < 9; k++) {
                    float lo, hi;
                    upk2(acc2[oc * 9 + k], lo, hi);
                    mx = fmaxf(mx, lo);
                    my = fmaxf(my, hi);
                }
                g_pool1[ob + oc * 1369] = fmaxf(mx + bsh[oc], 0.f);
                if (nrows == 2)
                    g_pool1[ob + oc * 1369 + 37] = fmaxf(my + bsh[oc], 0.f);
            }
        }
        __syncthreads();   // protect buf[g&1] before group g+2 overwrites it
    }
}

// ---------------------------------------------------------------------------
// Stage 2: conv2 + maxpool3 + relu + 36->6 linear. One block per image.
// Block 0 additionally streams stage3's big weights to warm L2.
// ---------------------------------------------------------------------------
__global__ __launch_bounds__(128) void stage2_kernel(
    const float* __restrict__ w2g,   // [1][3][3][3]
    const float* __restrict__ b2g,   // [1]
    const float* __restrict__ linw,  // [6][36]
    const float* __restrict__ linb,  // [6]
    const float* __restrict__ fc1w,  // warmed for stage3
    const float* __restrict__ fc2w)
{
    const int img = blockIdx.x;
    const int tid = threadIdx.x;

    __shared__ float s[3 * 1369];
    __shared__ float s2[36];

    const float* src = g_pool1 + (size_t)img * 4107;
    for (int i = tid; i < 4107; i += blockDim.x) s[i] = src[i];

    float w[27];
#pragma unroll
    for (int i = 0; i < 27; i++) w[i] = w2g[i];
    const float bias = b2g[0];

    if (img == 0) {
        float acc = 0.f;
        const float4* p1 = (const float4*)fc1w;
        for (int i = tid; i < 7200; i += 128) {
            float4 v = p1[i]; acc += v.x + v.y + v.z + v.w;
        }
        const float4* p2 = (const float4*)fc2w;
        for (int i = tid; i < 1800; i += 128) {
            float4 v = p2[i]; acc += v.x + v.y + v.z + v.w;
        }
        if (acc == -1.2345678e33f) g_sink = acc;   // never true; keeps loads live
    }
    __syncthreads();

    if (tid < 36) {
        const int pr = tid / 6, pc = tid - 6 * pr;
        float pool = -1e30f;
#pragma unroll
        for (int r = 0; r < 3; r++) {
#pragma unroll
            for (int c = 0; c < 3; c++) {
                const int R = 3 * pr + r;
                const int C = 3 * pc + c;
                float a = bias;
#pragma unroll
                for (int ci = 0; ci < 3; ci++)
#pragma unroll
                    for (int kh = 0; kh < 3; kh++)
#pragma unroll
                        for (int kw = 0; kw < 3; kw++)
                            a = fmaf(s[ci * 1369 + (2 * R + kh) * 37 + 2 * C + kw],
                                     w[ci * 9 + kh * 3 + kw], a);
                pool = fmaxf(pool, a);
            }
        }
        s2[tid] = fmaxf(pool, 0.f);
    }
    __syncthreads();

    if (tid < 6) {
        float a = linb[tid];
#pragma unroll
        for (int k = 0; k < 36; k++) a = fmaf(s2[k], linw[tid * 36 + k], a);
        g_nf[img * 6 + tid] = a;
    }
}

// ---------------------------------------------------------------------------
// Stage 3: message passing + MLP head. One block per node, 256 threads.
// ---------------------------------------------------------------------------
__global__ __launch_bounds__(256) void stage3_kernel(
    const float* __restrict__ pos,     // [64,5,4,6]
    const float* __restrict__ attmap,  // [64,5,4,4]
    const float* __restrict__ framew, const float* __restrict__ frameb,
    const float* __restrict__ lastw,  const float* __restrict__ lastb,
    const float* __restrict__ fc1w,   const float* __restrict__ fc1b,
    const float* __restrict__ fc2w,   const float* __restrict__ fc2b,
    const float* __restrict__ fc3w,   const float* __restrict__ fc3b,
    float* __restrict__ out)
{
    const int n   = blockIdx.x;
    const int tid = threadIdx.x;
    const int half = tid >> 7;        // 0 or 1
    const int o    = tid & 127;

    __shared__ __align__(16) float feat[240];
    __shared__ __align__(16) float h1[120];
    __shared__ __align__(16) float h2[60];
    __shared__ float part1[240];
    __shared__ float part2[120];
    __shared__ float part3[12];

    const float* posn = pos + n * 120;

    if (tid < 120) {
        const int f  = tid / 24;
        const int nn = (tid / 6) % 4;
        const int d  = tid % 6;
        const float* att = attmap + n * 80 + f * 16;

        feat[f * 48 + nn * 12 + d] = g_nf[(n * 20 + f * 4 + nn) * 6 + d];

        float acc = 0.f;
        const float fb = frameb[d];
#pragma unroll
        for (int j = 0; j < 4; j++) {
            float m = fb;
#pragma unroll
            for (int e = 0; e < 6; e++)
                m = fmaf(posn[(f * 4 + j) * 6 + e], framew[d * 6 + e], m);
            acc = fmaf(att[j * 4 + nn], m, acc);
        }
        if (f >= 1) {
            float l = lastb[d];
#pragma unroll
            for (int e = 0; e < 6; e++)
                l = fmaf(posn[((f - 1) * 4 + nn) * 6 + e], lastw[d * 6 + e], l);
            acc += l;
        }
        feat[f * 48 + nn * 12 + 6 + d] = acc;
    }
    __syncthreads();

    if (o < 120) {
        const float4* wr = (const float4*)(fc1w + o * 240 + half * 120);
        const float4* fe = (const float4*)feat + half * 30;
        float acc = 0.f;
#pragma unroll
        for (int k = 0; k < 30; k++) {
            float4 w4 = wr[k], f4 = fe[k];
            acc = fmaf(f4.x, w4.x, acc);
            acc = fmaf(f4.y, w4.y, acc);
            acc = fmaf(f4.z, w4.z, acc);
            acc = fmaf(f4.w, w4.w, acc);
        }
        part1[half * 120 + o] = acc;
    }
    __syncthreads();
    if (tid < 120) h1[tid] = fmaxf(part1[tid] + part1[120 + tid] + fc1b[tid], 0.f);
    __syncthreads();

    if (o < 60) {
        const float4* wr = (const float4*)(fc2w + o * 120 + half * 60);
        const float4* hh = (const float4*)h1 + half * 15;
        float acc = 0.f;
#pragma unroll
        for (int k = 0; k < 15; k++) {
            float4 w4 = wr[k], f4 = hh[k];
            acc = fmaf(f4.x, w4.x, acc);
            acc = fmaf(f4.y, w4.y, acc);
            acc = fmaf(f4.z, w4.z, acc);
            acc = fmaf(f4.w, w4.w, acc);
        }
        part2[half * 60 + o] = acc;
    }
    __syncthreads();
    if (tid < 60) h2[tid] = fmaxf(part2[tid] + part2[60 + tid] + fc2b[tid], 0.f);
    __syncthreads();

    if (o < 6) {
        const float2* wr = (const float2*)(fc3w + o * 60 + half * 30);
        const float2* hh = (const float2*)h2 + half * 15;
        float acc = 0.f;
#pragma unroll
        for (int k = 0; k < 15; k++) {
            float2 w2 = wr[k], f2 = hh[k];
            acc = fmaf(f2.x, w2.x, acc);
            acc = fmaf(f2.y, w2.y, acc);
        }
        part3[half * 6 + o] = acc;
    }
    __syncthreads();
    if (tid < 6) out[n * 6 + tid] = part3[tid] + part3[6 + tid] + fc3b[tid];
}

// ---------------------------------------------------------------------------
extern "C" void kernel_launch(void* const* d_in, const int* in_sizes, int n_in,
                              void* d_out, int out_size)
{
    const float* nodes  = (const float*)d_in[0];
    const float* pos    = (const float*)d_in[1];
    const float* attmap = (const float*)d_in[2];
    // d_in[3] = depths (unused)
    const float* conv1w = (const float*)d_in[4];
    const float* conv1b = (const float*)d_in[5];
    const float* conv2w = (const float*)d_in[6];
    const float* conv2b = (const float*)d_in[7];
    const float* linw   = (const float*)d_in[8];
    const float* linb   = (const float*)d_in[9];
    const float* framew = (const float*)d_in[10];
    const float* frameb = (const float*)d_in[11];
    const float* lastw  = (const float*)d_in[12];
    const float* lastb  = (const float*)d_in[13];
    const float* fc1w   = (const float*)d_in[14];
    const float* fc1b   = (const float*)d_in[15];
    const float* fc2w   = (const float*)d_in[16];
    const float* fc2b   = (const float*)d_in[17];
    const float* fc3w   = (const float*)d_in[18];
    const float* fc3b   = (const float*)d_in[19];

    cudaFuncSetAttribute(stage1_kernel,
                         cudaFuncAttributeMaxDynamicSharedMemorySize, S1_SMEM_BYTES);

    stage1_kernel<<<IMGS, 128, S1_SMEM_BYTES>>>(nodes, conv1w, conv1b);
    stage2_kernel<<<IMGS, 128>>>(conv2w, conv2b, linw, linb, fc1w, fc2w);
    stage3_kernel<<<64, 256>>>(pos, attmap, framew, frameb, lastw, lastb,
                               fc1w, fc1b, fc2w, fc2b, fc3w, fc3b,
                               (float*)d_out);
}

// round 13
// speedup vs baseline: 1.6082x; 1.6082x over previous
#include <cuda_runtime.h>
#include <cstddef>
#include <cstdint>

#define IMGS 1280

__device__ float g_pool1[IMGS * 3 * 37 * 37];   // 21 MB scratch
__device__ float g_nf[IMGS * 6];
__device__ float g_sink;                        // DCE-blocker for L2 warmup

// ---------------------------------------------------------------------------
// Stage 1: conv1(3->3,k3,s2) + maxpool3 + relu via cp.async double-buffered
// smem pipeline. Grid = 1280 (one image/block), 128 threads.
// 19 groups of 2 pooled rows; chunk prefetched with cp.async.cg while the
// previous group computes. Compute warps ROTATE with g: group g is handled by
// warps (g..g+2)&3 so all 4 SMSPs share the FMA stream across rounds.
// ---------------------------------------------------------------------------
#define CHUNK_F   8736
#define S1_SMEM_FLOATS (2 * CHUNK_F + 96)
#define S1_SMEM_BYTES  (S1_SMEM_FLOATS * 4)

__device__ __forceinline__ void cp_async16(uint32_t saddr, const void* gptr) {
    asm volatile("cp.async.cg.shared.global [%0], [%1], 16;\n"
                 :: "r"(saddr), "l"(gptr));
}

__global__ __launch_bounds__(128, 3) void stage1_kernel(
    const float* __restrict__ nodes,
    const float* __restrict__ w1g,     // [oc][ci][3][3]
    const float* __restrict__ b1g)     // [3]
{
    extern __shared__ float sm[];
    float* w1s = sm + 2 * CHUNK_F;      // [ci][oc][kh][kw] (81)
    float* bsh = w1s + 81;              // [3]

    const int tid  = threadIdx.x;
    const int wid  = tid >> 5;
    const int lane = tid & 31;
    const int img  = blockIdx.x;

    if (tid < 81) {
        int oc = tid / 27, rem = tid - oc * 27;
        int ci = rem / 9,  k   = rem - ci * 9;
        w1s[ci * 27 + oc * 9 + k] = w1g[tid];
    }
    if (tid < 3) bsh[tid] = b1g[tid];

    const float* src = nodes + (size_t)img * 150528;
    const uint32_t s_base = (uint32_t)__cvta_generic_to_shared(sm);

    auto load_group = [&](int g) {
        const int r0   = 12 * g;
        const int cnt  = (g == 18) ? 7 : 13;          // input rows
        const int n4   = cnt * 56;                     // float4 per channel
        const uint32_t dbase = s_base + ((g & 1) * CHUNK_F) * 4;
#pragma unroll 1
        for (int ci = 0; ci < 3; ci++) {
            const float* gsrc = src + ci * 50176 + r0 * 224;
            const uint32_t dch = dbase + ci * (2912 * 4);
            for (int i = tid; i < n4; i += 128)
                cp_async16(dch + i * 16, gsrc + i * 4);
        }
        asm volatile("cp.async.commit_group;\n" ::: "memory");
    };

    load_group(0);

#pragma unroll 1
    for (int g = 0; g < 19; g++) {
        if (g + 1 < 19) {
            load_group(g + 1);
            asm volatile("cp.async.wait_group 1;\n" ::: "memory");
        } else {
            asm volatile("cp.async.wait_group 0;\n" ::: "memory");
        }
        __syncthreads();

        const int p_base = 2 * g;
        const int nrows  = (g == 18) ? 1 : 2;
        const int cells  = nrows * 37;
        const float* buf = sm + (g & 1) * CHUNK_F;

        // rotated compute-warp assignment: warp slots 0..2 relative to g
        const int wslot   = (wid - g) & 3;
        const int cellIdx = wslot * 32 + lane;

        if (wslot < 3 && cellIdx < cells) {
            const int pl = cellIdx / 37;
            const int q  = cellIdx - pl * 37;

            float acc[3][3][3];   // [oc][pr][pc]
#pragma unroll
            for (int oc = 0; oc < 3; oc++)
#pragma unroll
                for (int pr = 0; pr < 3; pr++)
#pragma unroll
                    for (int pc = 0; pc < 3; pc++) acc[oc][pr][pc] = 0.f;

#pragma unroll
            for (int ci = 0; ci < 3; ci++) {
                float wl[27];
#pragma unroll
                for (int j = 0; j < 27; j++) wl[j] = w1s[ci * 27 + j];

                const float* base = buf + ci * 2912 + (6 * pl) * 224 + 6 * q;
#pragma unroll
                for (int r = 0; r < 7; r++) {
                    const float2* rp = (const float2*)(base + r * 224);
                    float2 a0 = rp[0], a1 = rp[1], a2 = rp[2], a3 = rp[3];
                    float v[7] = {a0.x, a0.y, a1.x, a1.y, a2.x, a2.y, a3.x};
#pragma unroll
                    for (int pr = 0; pr < 3; pr++) {
                        const int kh = r - 2 * pr;
                        if (kh >= 0 && kh < 3) {
#pragma unroll
                            for (int oc = 0; oc < 3; oc++)
#pragma unroll
                                for (int pc = 0; pc < 3; pc++)
#pragma unroll
                                    for (int kw = 0; kw < 3; kw++)
                                        acc[oc][pr][pc] =
                                            fmaf(v[2 * pc + kw],
                                                 wl[oc * 9 + kh * 3 + kw],
                                                 acc[oc][pr][pc]);
                        }
                    }
                }
            }

            const int p = p_base + pl;
            const size_t ob = (size_t)img * 4107 + (size_t)p * 37 + q;
#pragma unroll
            for (int oc = 0; oc < 3; oc++) {
                float m = acc[oc][0][0];
#pragma unroll
                for (int pr = 0; pr < 3; pr++)
#pragma unroll
                    for (int pc = 0; pc < 3; pc++) m = fmaxf(m, acc[oc][pr][pc]);
                g_pool1[ob + oc * 1369] = fmaxf(m + bsh[oc], 0.f);
            }
        }
        __syncthreads();   // protect buf[g&1] before group g+2 overwrites it
    }
}

// ---------------------------------------------------------------------------
// Stage 2: conv2 + maxpool3 + relu + 36->6 linear. One block per image.
// Block 0 additionally streams stage3's big weights to warm L2.
// ---------------------------------------------------------------------------
__global__ __launch_bounds__(128) void stage2_kernel(
    const float* __restrict__ w2g,   // [1][3][3][3]
    const float* __restrict__ b2g,   // [1]
    const float* __restrict__ linw,  // [6][36]
    const float* __restrict__ linb,  // [6]
    const float* __restrict__ fc1w,  // warmed for stage3
    const float* __restrict__ fc2w)
{
    const int img = blockIdx.x;
    const int tid = threadIdx.x;

    __shared__ float s[3 * 1369];
    __shared__ float s2[36];

    const float* src = g_pool1 + (size_t)img * 4107;
    for (int i = tid; i < 4107; i += blockDim.x) s[i] = src[i];

    float w[27];
#pragma unroll
    for (int i = 0; i < 27; i++) w[i] = w2g[i];
    const float bias = b2g[0];

    if (img == 0) {
        float acc = 0.f;
        const float4* p1 = (const float4*)fc1w;
        for (int i = tid; i < 7200; i += 128) {
            float4 v = p1[i]; acc += v.x + v.y + v.z + v.w;
        }
        const float4* p2 = (const float4*)fc2w;
        for (int i = tid; i < 1800; i += 128) {
            float4 v = p2[i]; acc += v.x + v.y + v.z + v.w;
        }
        if (acc == -1.2345678e33f) g_sink = acc;   // never true; keeps loads live
    }
    __syncthreads();

    if (tid < 36) {
        const int pr = tid / 6, pc = tid - 6 * pr;
        float pool = -1e30f;
#pragma unroll
        for (int r = 0; r < 3; r++) {
#pragma unroll
            for (int c = 0; c < 3; c++) {
                const int R = 3 * pr + r;
                const int C = 3 * pc + c;
                float a = bias;
#pragma unroll
                for (int ci = 0; ci < 3; ci++)
#pragma unroll
                    for (int kh = 0; kh < 3; kh++)
#pragma unroll
                        for (int kw = 0; kw < 3; kw++)
                            a = fmaf(s[ci * 1369 + (2 * R + kh) * 37 + 2 * C + kw],
                                     w[ci * 9 + kh * 3 + kw], a);
                pool = fmaxf(pool, a);
            }
        }
        s2[tid] = fmaxf(pool, 0.f);
    }
    __syncthreads();

    if (tid < 6) {
        float a = linb[tid];
#pragma unroll
        for (int k = 0; k < 36; k++) a = fmaf(s2[k], linw[tid * 36 + k], a);
        g_nf[img * 6 + tid] = a;
    }
}

// ---------------------------------------------------------------------------
// Stage 3: message passing + MLP head. One block per node, 256 threads.
// ---------------------------------------------------------------------------
__global__ __launch_bounds__(256) void stage3_kernel(
    const float* __restrict__ pos,     // [64,5,4,6]
    const float* __restrict__ attmap,  // [64,5,4,4]
    const float* __restrict__ framew, const float* __restrict__ frameb,
    const float* __restrict__ lastw,  const float* __restrict__ lastb,
    const float* __restrict__ fc1w,   const float* __restrict__ fc1b,
    const float* __restrict__ fc2w,   const float* __restrict__ fc2b,
    const float* __restrict__ fc3w,   const float* __restrict__ fc3b,
    float* __restrict__ out)
{
    const int n   = blockIdx.x;
    const int tid = threadIdx.x;
    const int half = tid >> 7;        // 0 or 1
    const int o    = tid & 127;

    __shared__ __align__(16) float feat[240];
    __shared__ __align__(16) float h1[120];
    __shared__ __align__(16) float h2[60];
    __shared__ float part1[240];
    __shared__ float part2[120];
    __shared__ float part3[12];

    const float* posn = pos + n * 120;

    if (tid < 120) {
        const int f  = tid / 24;
        const int nn = (tid / 6) % 4;
        const int d  = tid % 6;
        const float* att = attmap + n * 80 + f * 16;

        feat[f * 48 + nn * 12 + d] = g_nf[(n * 20 + f * 4 + nn) * 6 + d];

        float acc = 0.f;
        const float fb = frameb[d];
#pragma unroll
        for (int j = 0; j < 4; j++) {
            float m = fb;
#pragma unroll
            for (int e = 0; e < 6; e++)
                m = fmaf(posn[(f * 4 + j) * 6 + e], framew[d * 6 + e], m);
            acc = fmaf(att[j * 4 + nn], m, acc);
        }
        if (f >= 1) {
            float l = lastb[d];
#pragma unroll
            for (int e = 0; e < 6; e++)
                l = fmaf(posn[((f - 1) * 4 + nn) * 6 + e], lastw[d * 6 + e], l);
            acc += l;
        }
        feat[f * 48 + nn * 12 + 6 + d] = acc;
    }
    __syncthreads();

    if (o < 120) {
        const float4* wr = (const float4*)(fc1w + o * 240 + half * 120);
        const float4* fe = (const float4*)feat + half * 30;
        float acc = 0.f;
#pragma unroll
        for (int k = 0; k < 30; k++) {
            float4 w4 = wr[k], f4 = fe[k];
            acc = fmaf(f4.x, w4.x, acc);
            acc = fmaf(f4.y, w4.y, acc);
            acc = fmaf(f4.z, w4.z, acc);
            acc = fmaf(f4.w, w4.w, acc);
        }
        part1[half * 120 + o] = acc;
    }
    __syncthreads();
    if (tid < 120) h1[tid] = fmaxf(part1[tid] + part1[120 + tid] + fc1b[tid], 0.f);
    __syncthreads();

    if (o < 60) {
        const float4* wr = (const float4*)(fc2w + o * 120 + half * 60);
        const float4* hh = (const float4*)h1 + half * 15;
        float acc = 0.f;
#pragma unroll
        for (int k = 0; k < 15; k++) {
            float4 w4 = wr[k], f4 = hh[k];
            acc = fmaf(f4.x, w4.x, acc);
            acc = fmaf(f4.y, w4.y, acc);
            acc = fmaf(f4.z, w4.z, acc);
            acc = fmaf(f4.w, w4.w, acc);
        }
        part2[half * 60 + o] = acc;
    }
    __syncthreads();
    if (tid < 60) h2[tid] = fmaxf(part2[tid] + part2[60 + tid] + fc2b[tid], 0.f);
    __syncthreads();

    if (o < 6) {
        const float2* wr = (const float2*)(fc3w + o * 60 + half * 30);
        const float2* hh = (const float2*)h2 + half * 15;
        float acc = 0.f;
#pragma unroll
        for (int k = 0; k < 15; k++) {
            float2 w2 = wr[k], f2 = hh[k];
            acc = fmaf(f2.x, w2.x, acc);
            acc = fmaf(f2.y, w2.y, acc);
        }
        part3[half * 6 + o] = acc;
    }
    __syncthreads();
    if (tid < 6) out[n * 6 + tid] = part3[tid] + part3[6 + tid] + fc3b[tid];
}

// ---------------------------------------------------------------------------
extern "C" void kernel_launch(void* const* d_in, const int* in_sizes, int n_in,
                              void* d_out, int out_size)
{
    const float* nodes  = (const float*)d_in[0];
    const float* pos    = (const float*)d_in[1];
    const float* attmap = (const float*)d_in[2];
    // d_in[3] = depths (unused)
    const float* conv1w = (const float*)d_in[4];
    const float* conv1b = (const float*)d_in[5];
    const float* conv2w = (const float*)d_in[6];
    const float* conv2b = (const float*)d_in[7];
    const float* linw   = (const float*)d_in[8];
    const float* linb   = (const float*)d_in[9];
    const float* framew = (const float*)d_in[10];
    const float* frameb = (const float*)d_in[11];
    const float* lastw  = (const float*)d_in[12];
    const float* lastb  = (const float*)d_in[13];
    const float* fc1w   = (const float*)d_in[14];
    const float* fc1b   = (const float*)d_in[15];
    const float* fc2w   = (const float*)d_in[16];
    const float* fc2b   = (const float*)d_in[17];
    const float* fc3w   = (const float*)d_in[18];
    const float* fc3b   = (const float*)d_in[19];

    cudaFuncSetAttribute(stage1_kernel,
                         cudaFuncAttributeMaxDynamicSharedMemorySize, S1_SMEM_BYTES);

    stage1_kernel<<<IMGS, 128, S1_SMEM_BYTES>>>(nodes, conv1w, conv1b);
    stage2_kernel<<<IMGS, 128>>>(conv2w, conv2b, linw, linb, fc1w, fc2w);
    stage3_kernel<<<64, 256>>>(pos, attmap, framew, frameb, lastw, lastb,
                               fc1w, fc1b, fc2w, fc2b, fc3w, fc3b,
                               (float*)d_out);
}